// round 5
// baseline (speedup 1.0000x reference)
#include <cuda_runtime.h>
#include <cuda_bf16.h>
#include <cstdint>
#include <cstddef>

#define MBATCH 16
#define LEN    1024
#define EMB    1024
#define NHEAD  8
#define HD     128
#define MROWS  (MBATCH*LEN)   // 16384
#define NHB    (NHEAD*MBATCH) // 128

// ---------------- scratch ----------------
__device__ float g_sk[NHB*LEN];
__device__ float g_sq[NHB*LEN];
__device__ float g_invd[NHB*LEN];
__device__ float g_Vk[NHEAD*EMB];
__device__ float g_Vq[NHEAD*EMB];
__device__ float g_ck[NHEAD];
__device__ float g_cq[NHEAD];
__device__ __nv_bfloat16 g_kh[(size_t)MROWS*EMB];
__device__ __nv_bfloat16 g_kl[(size_t)MROWS*EMB];
__device__ __nv_bfloat16 g_kxh[(size_t)MROWS*EMB];
__device__ __nv_bfloat16 g_kxl[(size_t)MROWS*EMB];
__device__ __nv_bfloat16 g_ah[(size_t)MROWS*EMB];
__device__ __nv_bfloat16 g_al[(size_t)MROWS*EMB];
__device__ __nv_bfloat16 g_Wkh[(size_t)EMB*EMB];
__device__ __nv_bfloat16 g_Wkl[(size_t)EMB*EMB];
__device__ __nv_bfloat16 g_Wph[(size_t)EMB*EMB];
__device__ __nv_bfloat16 g_Wpl[(size_t)EMB*EMB];

// ---------------- helpers ----------------
__device__ __forceinline__ uint32_t smem_u32(const void* p) {
    uint32_t a;
    asm("{ .reg .u64 t; cvta.to.shared.u64 t, %1; cvt.u32.u64 %0, t; }" : "=r"(a) : "l"(p));
    return a;
}
__device__ __forceinline__ void cpa16(uint32_t s, const void* g) {
    asm volatile("cp.async.cg.shared.global [%0], [%1], 16;" :: "r"(s), "l"(g));
}
#define CPA_COMMIT() asm volatile("cp.async.commit_group;" ::: "memory")
#define CPA_WAIT1()  asm volatile("cp.async.wait_group 1;" ::: "memory")

__device__ __forceinline__ void ldsm4(uint32_t* r, uint32_t a) {
    asm volatile("ldmatrix.sync.aligned.m8n8.x4.shared.b16 {%0,%1,%2,%3}, [%4];"
        : "=r"(r[0]), "=r"(r[1]), "=r"(r[2]), "=r"(r[3]) : "r"(a));
}
__device__ __forceinline__ void ldsm4t(uint32_t* r, uint32_t a) {
    asm volatile("ldmatrix.sync.aligned.m8n8.x4.trans.shared.b16 {%0,%1,%2,%3}, [%4];"
        : "=r"(r[0]), "=r"(r[1]), "=r"(r[2]), "=r"(r[3]) : "r"(a));
}
__device__ __forceinline__ void mma_bf16(float* c, const uint32_t* a, const uint32_t* b) {
    asm volatile(
        "mma.sync.aligned.m16n8k16.row.col.f32.bf16.bf16.f32 "
        "{%0,%1,%2,%3}, {%4,%5,%6,%7}, {%8,%9}, {%0,%1,%2,%3};"
        : "+f"(c[0]), "+f"(c[1]), "+f"(c[2]), "+f"(c[3])
        : "r"(a[0]), "r"(a[1]), "r"(a[2]), "r"(a[3]), "r"(b[0]), "r"(b[1]));
}
__device__ __forceinline__ float exp_tanh(float x) {
    float t;
    asm("tanh.approx.f32 %0, %1;" : "=f"(t) : "f"(x));
    return __expf(t);
}
__device__ __forceinline__ uint32_t pack_bf16(float a, float b) {
    __nv_bfloat162 v = {__float2bfloat16(a), __float2bfloat16(b)};
    return *(uint32_t*)&v;
}

// ---------------------------------------------------------------------------
// split fp32 -> bf16 hi + lo.  16 floats per thread, 4 independent float4
// loads up front (MLP=4).
// ---------------------------------------------------------------------------
__global__ __launch_bounds__(256) void split_kernel(
    const float* __restrict__ x, __nv_bfloat16* __restrict__ h,
    __nv_bfloat16* __restrict__ l, int n)
{
    int base = (blockIdx.x * 256 + threadIdx.x) * 16;
    if (base >= n) return;
    float4 v[4];
    #pragma unroll
    for (int i = 0; i < 4; i++) v[i] = *(const float4*)(x + base + i * 4);
    #pragma unroll
    for (int i = 0; i < 4; i++) {
        __nv_bfloat16 h0 = __float2bfloat16(v[i].x), h1 = __float2bfloat16(v[i].y);
        __nv_bfloat16 h2 = __float2bfloat16(v[i].z), h3 = __float2bfloat16(v[i].w);
        __nv_bfloat16 l0 = __float2bfloat16(v[i].x - __bfloat162float(h0));
        __nv_bfloat16 l1 = __float2bfloat16(v[i].y - __bfloat162float(h1));
        __nv_bfloat16 l2 = __float2bfloat16(v[i].z - __bfloat162float(h2));
        __nv_bfloat16 l3 = __float2bfloat16(v[i].w - __bfloat162float(h3));
        ((__nv_bfloat162*)(h + base + i * 4))[0] = {h0, h1};
        ((__nv_bfloat162*)(h + base + i * 4))[1] = {h2, h3};
        ((__nv_bfloat162*)(l + base + i * 4))[0] = {l0, l1};
        ((__nv_bfloat162*)(l + base + i * 4))[1] = {l2, l3};
    }
}

// ---------------------------------------------------------------------------
// Vk[h,e] = sum_c Wk[h*128+c, e] * w[c] ; ck[h] = sum_c bk[h*128+c]*w[c]
// grid (8 heads, 8 e-chunks), 128 threads; thread owns one e.
// ---------------------------------------------------------------------------
__global__ __launch_bounds__(128) void vkq_kernel(
    const float* __restrict__ Wk, const float* __restrict__ bk,
    const float* __restrict__ Wq, const float* __restrict__ bq,
    const float* __restrict__ w)
{
    const int h = blockIdx.x;
    const int e = blockIdx.y * 128 + threadIdx.x;
    const int tid = threadIdx.x;
    const float* rK = Wk + (size_t)(h * HD) * EMB + e;
    const float* rQ = Wq + (size_t)(h * HD) * EMB + e;
    float aK = 0.0f, aQ = 0.0f;
    #pragma unroll 4
    for (int c = 0; c < HD; c++) {
        aK += rK[(size_t)c * EMB] * __ldg(w + c);
        aQ += rQ[(size_t)c * EMB] * __ldg(w + HD + c);
    }
    g_Vk[h * EMB + e] = aK;
    g_Vq[h * EMB + e] = aQ;

    if (blockIdx.y == 0) {
        __shared__ float red[128];
        red[tid] = bk[h * HD + tid] * w[tid];
        __syncthreads();
        for (int s = 64; s; s >>= 1) { if (tid < s) red[tid] += red[tid + s]; __syncthreads(); }
        if (tid == 0) g_ck[h] = red[0];
        __syncthreads();
        red[tid] = bq[h * HD + tid] * w[HD + tid];
        __syncthreads();
        for (int s = 64; s; s >>= 1) { if (tid < s) red[tid] += red[tid + s]; __syncthreads(); }
        if (tid == 0) g_cq[h] = red[0];
    }
}

// ---------------------------------------------------------------------------
// sk[hb,j] = k[b,j,:]·Vk[h] + ck[h];  sq likewise.  warp per (b,j).
// ---------------------------------------------------------------------------
__global__ __launch_bounds__(256) void sksq_kernel(
    const float* __restrict__ k, const float* __restrict__ q)
{
    const int gw = (blockIdx.x * 256 + threadIdx.x) >> 5;
    const int lane = threadIdx.x & 31;
    const int b = gw >> 10, j = gw & 1023;
    const float* kr = k + (size_t)gw * EMB;
    const float* qr = q + (size_t)gw * EMB;
    float aK[8] = {0,0,0,0,0,0,0,0}, aQ[8] = {0,0,0,0,0,0,0,0};
    for (int t = 0; t < 8; t++) {
        int idx = t*128 + (lane << 2);
        float4 kv = *(const float4*)(kr + idx);
        float4 qv = *(const float4*)(qr + idx);
        #pragma unroll
        for (int h = 0; h < 8; h++) {
            float4 vk = *(const float4*)(g_Vk + h*EMB + idx);
            float4 vq = *(const float4*)(g_Vq + h*EMB + idx);
            aK[h] += kv.x*vk.x + kv.y*vk.y + kv.z*vk.z + kv.w*vk.w;
            aQ[h] += qv.x*vq.x + qv.y*vq.y + qv.z*vq.z + qv.w*vq.w;
        }
    }
    #pragma unroll
    for (int h = 0; h < 8; h++)
        #pragma unroll
        for (int o = 16; o; o >>= 1) {
            aK[h] += __shfl_xor_sync(0xffffffffu, aK[h], o);
            aQ[h] += __shfl_xor_sync(0xffffffffu, aQ[h], o);
        }
    if (lane < 8) {
        int h = lane;
        g_sk[(size_t)(h*MBATCH + b)*LEN + j] = aK[h] + g_ck[h];
        g_sq[(size_t)(h*MBATCH + b)*LEN + j] = aQ[h] + g_cq[h];
    }
}

// ---------------------------------------------------------------------------
// inv_d[hb,i] = 1 / sum_j exp(tanh(sq_i + sk_j))
// ---------------------------------------------------------------------------
__global__ __launch_bounds__(128) void denom_kernel()
{
    __shared__ float sks[LEN];
    const int hb = blockIdx.x >> 3;
    const int i0 = (blockIdx.x & 7) << 7;
    for (int t = threadIdx.x; t < LEN; t += 128) sks[t] = g_sk[hb * LEN + t];
    __syncthreads();
    const int i = i0 + threadIdx.x;
    const float sqi = g_sq[hb * LEN + i];
    float s = 0.0f;
    #pragma unroll 8
    for (int j = 0; j < LEN; j++) s += exp_tanh(sqi + sks[j]);
    g_invd[hb * LEN + i] = __fdividef(1.0f, s);
}

// ---------------------------------------------------------------------------
// mma.sync split-bf16 GEMM, 3-stage cp.async pipeline, 1 sync/iter.
// ---------------------------------------------------------------------------
#define PADROW  40
#define PLANE_B (128*PADROW*2)
#define OFF_AH  0
#define OFF_AL  (PLANE_B)
#define OFF_BH  (2*PLANE_B)
#define OFF_BL  (3*PLANE_B)
#define BUF_B   (4*PLANE_B)
#define GEMM_SMEM (3*BUF_B)
#define NCH     32

__global__ __launch_bounds__(256) void gemm_mma(
    const __nv_bfloat16* __restrict__ Ah, const __nv_bfloat16* __restrict__ Al,
    const __nv_bfloat16* __restrict__ Bh, const __nv_bfloat16* __restrict__ Bl,
    const float* __restrict__ bias, float* __restrict__ C,
    __nv_bfloat16* __restrict__ Ch, __nv_bfloat16* __restrict__ Cl)
{
    extern __shared__ char smem[];
    const uint32_t sb = smem_u32(smem);
    const int tid = threadIdx.x;
    const int wid = tid >> 5, lane = tid & 31;
    const int g = lane >> 2, tig = lane & 3;
    const int m0 = blockIdx.y << 7, n0 = blockIdx.x << 7;
    const int wm = (wid & 1) << 6;
    const int wn = (wid >> 1) << 5;
    const uint32_t lrow = lane & 15, lhalf = (lane >> 4) * 16;

    const int lr = tid >> 1;
    const int lc = (tid & 1) * 2;
    const uint32_t s_off = lr * 80 + lc * 16;
    const __nv_bfloat16* gAh = Ah + (size_t)(m0 + lr) * 1024 + lc * 8;
    const __nv_bfloat16* gAl = Al + (size_t)(m0 + lr) * 1024 + lc * 8;
    const __nv_bfloat16* gBh = Bh + (size_t)(n0 + lr) * 1024 + lc * 8;
    const __nv_bfloat16* gBl = Bl + (size_t)(n0 + lr) * 1024 + lc * 8;

    float acc[4][4][4];
    #pragma unroll
    for (int i = 0; i < 4; i++)
        #pragma unroll
        for (int j = 0; j < 4; j++)
            #pragma unroll
            for (int r = 0; r < 4; r++) acc[i][j][r] = 0.0f;

    #pragma unroll
    for (int pc = 0; pc < 2; pc++) {
        uint32_t d = sb + pc * BUF_B + s_off;
        size_t gk = (size_t)pc * 32;
        cpa16(d + OFF_AH, gAh + gk);      cpa16(d + OFF_AH + 16, gAh + gk + 8);
        cpa16(d + OFF_AL, gAl + gk);      cpa16(d + OFF_AL + 16, gAl + gk + 8);
        cpa16(d + OFF_BH, gBh + gk);      cpa16(d + OFF_BH + 16, gBh + gk + 8);
        cpa16(d + OFF_BL, gBl + gk);      cpa16(d + OFF_BL + 16, gBl + gk + 8);
        CPA_COMMIT();
    }

    for (int c = 0; c < NCH; c++) {
        CPA_WAIT1();
        __syncthreads();
        if (c + 2 < NCH) {
            uint32_t d = sb + ((c + 2) % 3) * BUF_B + s_off;
            size_t gk = (size_t)(c + 2) * 32;
            cpa16(d + OFF_AH, gAh + gk);      cpa16(d + OFF_AH + 16, gAh + gk + 8);
            cpa16(d + OFF_AL, gAl + gk);      cpa16(d + OFF_AL + 16, gAl + gk + 8);
            cpa16(d + OFF_BH, gBh + gk);      cpa16(d + OFF_BH + 16, gBh + gk + 8);
            cpa16(d + OFF_BL, gBl + gk);      cpa16(d + OFF_BL + 16, gBl + gk + 8);
        }
        CPA_COMMIT();

        const uint32_t bp = sb + (c % 3) * BUF_B;
        #pragma unroll
        for (int ks = 0; ks < 2; ks++) {
            const uint32_t kb = ks * 32;
            uint32_t ah[4][4], al[4][4], bh[4][2], bl[4][2];
            #pragma unroll
            for (int mf = 0; mf < 4; mf++) {
                uint32_t ra = bp + (wm + mf*16 + lrow) * 80 + kb + lhalf;
                ldsm4(ah[mf], ra + OFF_AH);
                ldsm4(al[mf], ra + OFF_AL);
            }
            #pragma unroll
            for (int nh = 0; nh < 2; nh++) {
                uint32_t rb = bp + (wn + nh*16 + lrow) * 80 + kb + lhalf;
                uint32_t t[4];
                ldsm4(t, rb + OFF_BH);
                bh[nh*2][0] = t[0]; bh[nh*2][1] = t[2];
                bh[nh*2+1][0] = t[1]; bh[nh*2+1][1] = t[3];
                ldsm4(t, rb + OFF_BL);
                bl[nh*2][0] = t[0]; bl[nh*2][1] = t[2];
                bl[nh*2+1][0] = t[1]; bl[nh*2+1][1] = t[3];
            }
            #pragma unroll
            for (int mf = 0; mf < 4; mf++)
                #pragma unroll
                for (int nf = 0; nf < 4; nf++) {
                    mma_bf16(acc[mf][nf], ah[mf], bh[nf]);
                    mma_bf16(acc[mf][nf], ah[mf], bl[nf]);
                    mma_bf16(acc[mf][nf], al[mf], bh[nf]);
                }
        }
    }

    #pragma unroll
    for (int mf = 0; mf < 4; mf++) {
        #pragma unroll
        for (int nf = 0; nf < 4; nf++) {
            const int row = m0 + wm + mf * 16 + g;
            const int col = n0 + wn + nf * 8 + 2 * tig;
            const float b0 = bias[col], b1 = bias[col + 1];
            float v00 = acc[mf][nf][0] + b0, v01 = acc[mf][nf][1] + b1;
            float v10 = acc[mf][nf][2] + b0, v11 = acc[mf][nf][3] + b1;
            if (C) {
                *(float2*)(C + (size_t)row * 1024 + col) = {v00, v01};
                *(float2*)(C + (size_t)(row + 8) * 1024 + col) = {v10, v11};
            }
            if (Ch) {
                uint32_t h0 = pack_bf16(v00, v01), h1 = pack_bf16(v10, v11);
                float r00 = v00 - __bfloat162float(__float2bfloat16(v00));
                float r01 = v01 - __bfloat162float(__float2bfloat16(v01));
                float r10 = v10 - __bfloat162float(__float2bfloat16(v10));
                float r11 = v11 - __bfloat162float(__float2bfloat16(v11));
                *(uint32_t*)(Ch + (size_t)row * 1024 + col) = h0;
                *(uint32_t*)(Ch + (size_t)(row + 8) * 1024 + col) = h1;
                *(uint32_t*)(Cl + (size_t)row * 1024 + col) = pack_bf16(r00, r01);
                *(uint32_t*)(Cl + (size_t)(row + 8) * 1024 + col) = pack_bf16(r10, r11);
            }
        }
    }
}

// ---------------------------------------------------------------------------
// Fused attention, 3-stage pipeline, 1 sync/iter.
// ---------------------------------------------------------------------------
#define A_SK   0
#define A_SQ   4096
#define A_ID   4608
#define A_ST   5120
#define A_PH   0
#define A_PL   10240
#define A_KH   20480
#define A_KL   29184
#define A_STB  37888
#define ATTN_SMEM (A_ST + 3*A_STB)

__global__ __launch_bounds__(256) void attn_mma(
    const __nv_bfloat16* __restrict__ kxh, const __nv_bfloat16* __restrict__ kxl,
    float* __restrict__ score,
    __nv_bfloat16* __restrict__ aout_h, __nv_bfloat16* __restrict__ aout_l)
{
    extern __shared__ char smem[];
    const uint32_t sb = smem_u32(smem);
    float* sksA = (float*)smem;
    float* sqsA = (float*)(smem + A_SQ);
    float* idsA = (float*)(smem + A_ID);

    const int tid = threadIdx.x;
    const int wid = tid >> 5, lane = tid & 31;
    const int g = lane >> 2, tig = lane & 3;
    const int hb = blockIdx.y;
    const int h = hb >> 4, b = hb & 15;
    const int i0 = blockIdx.x << 7;
    const int wm = (wid & 1) << 6;
    const int wn = (wid >> 1) << 5;
    const uint32_t lrow = lane & 15, lhalf = (lane >> 4) * 16;

    for (int t = tid; t < LEN; t += 256) sksA[t] = g_sk[hb * LEN + t];
    if (tid < 128) {
        sqsA[tid] = g_sq[hb * LEN + i0 + tid];
        idsA[tid] = g_invd[hb * LEN + i0 + tid];
    }
    __syncthreads();

    const int prow = tid >> 1;
    const int pj0 = (tid & 1) * 16;
    const float sqi = sqsA[prow];
    const float idi = idsA[prow];
    float* srow = score + ((size_t)hb * LEN + i0 + prow) * LEN + pj0;
    const uint32_t p_off = prow * 80 + pj0 * 2;

    const int krow = tid >> 3;
    const int kseg = tid & 7;
    const __nv_bfloat16* gKh = kxh + (size_t)(b * 1024 + krow) * 1024 + h * 128 + kseg * 8;
    const __nv_bfloat16* gKl = kxl + (size_t)(b * 1024 + krow) * 1024 + h * 128 + kseg * 8;
    const uint32_t k_off = krow * 272 + kseg * 16;

    float acc[4][4][4];
    #pragma unroll
    for (int i = 0; i < 4; i++)
        #pragma unroll
        for (int j = 0; j < 4; j++)
            #pragma unroll
            for (int r = 0; r < 4; r++) acc[i][j][r] = 0.0f;

    #define GEN_CHUNK(ch, stbase) do {                                          \
        const int jb = (ch) * 32;                                               \
        float pf[16]; uint32_t hp[8], lp[8];                                    \
        _Pragma("unroll")                                                       \
        for (int u = 0; u < 16; u++)                                            \
            pf[u] = exp_tanh(sqi + sksA[jb + pj0 + u]) * idi;                   \
        _Pragma("unroll")                                                       \
        for (int u = 0; u < 8; u++) {                                           \
            float p0 = pf[2*u], p1 = pf[2*u+1];                                 \
            hp[u] = pack_bf16(p0, p1);                                          \
            float r0 = p0 - __bfloat162float(__float2bfloat16(p0));             \
            float r1 = p1 - __bfloat162float(__float2bfloat16(p1));             \
            lp[u] = pack_bf16(r0, r1);                                          \
        }                                                                       \
        *(float4*)(srow + jb)      = {pf[0], pf[1], pf[2], pf[3]};              \
        *(float4*)(srow + jb + 4)  = {pf[4], pf[5], pf[6], pf[7]};              \
        *(float4*)(srow + jb + 8)  = {pf[8], pf[9], pf[10], pf[11]};            \
        *(float4*)(srow + jb + 12) = {pf[12], pf[13], pf[14], pf[15]};          \
        asm volatile("st.shared.v4.b32 [%0], {%1,%2,%3,%4};" ::                 \
            "r"((stbase) + A_PH + p_off), "r"(hp[0]), "r"(hp[1]), "r"(hp[2]), "r"(hp[3]) : "memory"); \
        asm volatile("st.shared.v4.b32 [%0], {%1,%2,%3,%4};" ::                 \
            "r"((stbase) + A_PH + p_off + 16), "r"(hp[4]), "r"(hp[5]), "r"(hp[6]), "r"(hp[7]) : "memory"); \
        asm volatile("st.shared.v4.b32 [%0], {%1,%2,%3,%4};" ::                 \
            "r"((stbase) + A_PL + p_off), "r"(lp[0]), "r"(lp[1]), "r"(lp[2]), "r"(lp[3]) : "memory"); \
        asm volatile("st.shared.v4.b32 [%0], {%1,%2,%3,%4};" ::                 \
            "r"((stbase) + A_PL + p_off + 16), "r"(lp[4]), "r"(lp[5]), "r"(lp[6]), "r"(lp[7]) : "memory"); \
        const size_t gkoff = (size_t)jb * 1024;                                 \
        cpa16((stbase) + A_KH + k_off,       gKh + gkoff);                      \
        cpa16((stbase) + A_KH + k_off + 128, gKh + gkoff + 64);                 \
        cpa16((stbase) + A_KL + k_off,       gKl + gkoff);                      \
        cpa16((stbase) + A_KL + k_off + 128, gKl + gkoff + 64);                 \
    } while (0)

    GEN_CHUNK(0, sb + A_ST);
    CPA_COMMIT();
    GEN_CHUNK(1, sb + A_ST + A_STB);
    CPA_COMMIT();

    for (int c = 0; c < 32; c++) {
        CPA_WAIT1();
        __syncthreads();
        if (c + 2 < 32) GEN_CHUNK(c + 2, sb + A_ST + ((c + 2) % 3) * A_STB);
        CPA_COMMIT();

        const uint32_t stb = sb + A_ST + (c % 3) * A_STB;
        #pragma unroll
        for (int ks = 0; ks < 2; ks++) {
            const uint32_t kb = ks * 32;
            uint32_t ph[4][4], pl[4][4], bh[4][2], bl[4][2];
            #pragma unroll
            for (int mf = 0; mf < 4; mf++) {
                uint32_t ra = stb + (wm + mf*16 + lrow) * 80 + kb + lhalf;
                ldsm4(ph[mf], ra + A_PH);
                ldsm4(pl[mf], ra + A_PL);
            }
            #pragma unroll
            for (int nh = 0; nh < 2; nh++) {
                uint32_t rb = stb + (ks*16 + lrow) * 272 + (wn + nh*16) * 2 + lhalf;
                uint32_t t[4];
                ldsm4t(t, rb + A_KH);
                bh[nh*2][0] = t[0]; bh[nh*2][1] = t[1];
                bh[nh*2+1][0] = t[2]; bh[nh*2+1][1] = t[3];
                ldsm4t(t, rb + A_KL);
                bl[nh*2][0] = t[0]; bl[nh*2][1] = t[1];
                bl[nh*2+1][0] = t[2]; bl[nh*2+1][1] = t[3];
            }
            #pragma unroll
            for (int mf = 0; mf < 4; mf++)
                #pragma unroll
                for (int nf = 0; nf < 4; nf++) {
                    mma_bf16(acc[mf][nf], ph[mf], bh[nf]);
                    mma_bf16(acc[mf][nf], ph[mf], bl[nf]);
                    mma_bf16(acc[mf][nf], pl[mf], bh[nf]);
                }
        }
    }

    #pragma unroll
    for (int mf = 0; mf < 4; mf++) {
        #pragma unroll
        for (int nf = 0; nf < 4; nf++) {
            const int r0 = wm + mf * 16 + g;
            const int col = wn + nf * 8 + 2 * tig;
            float v00 = acc[mf][nf][0], v01 = acc[mf][nf][1];
            float v10 = acc[mf][nf][2], v11 = acc[mf][nf][3];
            size_t o0 = (size_t)(b * 1024 + i0 + r0) * 1024 + h * 128 + col;
            size_t o1 = (size_t)(b * 1024 + i0 + r0 + 8) * 1024 + h * 128 + col;
            *(uint32_t*)(aout_h + o0) = pack_bf16(v00, v01);
            *(uint32_t*)(aout_h + o1) = pack_bf16(v10, v11);
            float r00 = v00 - __bfloat162float(__float2bfloat16(v00));
            float r01 = v01 - __bfloat162float(__float2bfloat16(v01));
            float r10 = v10 - __bfloat162float(__float2bfloat16(v10));
            float r11 = v11 - __bfloat162float(__float2bfloat16(v11));
            *(uint32_t*)(aout_l + o0) = pack_bf16(r00, r01);
            *(uint32_t*)(aout_l + o1) = pack_bf16(r10, r11);
        }
    }
}

// ---------------------------------------------------------------------------
extern "C" void kernel_launch(void* const* d_in, const int* in_sizes, int n_in,
                              void* d_out, int out_size)
{
    const float* k  = (const float*)d_in[0];
    const float* q  = (const float*)d_in[1];
    const float* Wk = (const float*)d_in[2];
    const float* bk = (const float*)d_in[3];
    const float* Wq = (const float*)d_in[4];
    const float* bq = (const float*)d_in[5];
    const float* w  = (const float*)d_in[6];
    const float* Wp = (const float*)d_in[7];
    const float* bp = (const float*)d_in[8];
    float* out   = (float*)d_out;
    float* score = out + (size_t)MROWS * EMB;

    __nv_bfloat16 *kh,*kl,*kxh,*kxl,*ah,*al,*wkh,*wkl,*wph,*wpl;
    cudaGetSymbolAddress((void**)&kh,  g_kh);   cudaGetSymbolAddress((void**)&kl,  g_kl);
    cudaGetSymbolAddress((void**)&kxh, g_kxh);  cudaGetSymbolAddress((void**)&kxl, g_kxl);
    cudaGetSymbolAddress((void**)&ah,  g_ah);   cudaGetSymbolAddress((void**)&al,  g_al);
    cudaGetSymbolAddress((void**)&wkh, g_Wkh);  cudaGetSymbolAddress((void**)&wkl, g_Wkl);
    cudaGetSymbolAddress((void**)&wph, g_Wph);  cudaGetSymbolAddress((void**)&wpl, g_Wpl);

    cudaFuncSetAttribute(gemm_mma, cudaFuncAttributeMaxDynamicSharedMemorySize, GEMM_SMEM);
    cudaFuncSetAttribute(attn_mma, cudaFuncAttributeMaxDynamicSharedMemorySize, ATTN_SMEM);

    const int nBig = MROWS * EMB;
    const int nW   = EMB * EMB;
    split_kernel<<<nBig/16/256, 256>>>(k, kh, kl, nBig);
    split_kernel<<<nW/16/256, 256>>>(Wk, wkh, wkl, nW);
    split_kernel<<<nW/16/256, 256>>>(Wp, wph, wpl, nW);

    vkq_kernel<<<dim3(NHEAD, 8), 128>>>(Wk, bk, Wq, bq, w);
    sksq_kernel<<<MROWS/8, 256>>>(k, q);
    denom_kernel<<<NHB * 8, 128>>>();

    dim3 gg(EMB / 128, MROWS / 128);
    gemm_mma<<<gg, 256, GEMM_SMEM>>>(kh, kl, wkh, wkl, bk, nullptr, kxh, kxl);
    attn_mma<<<dim3(8, NHB), 256, ATTN_SMEM>>>(kxh, kxl, score, ah, al);
    gemm_mma<<<gg, 256, GEMM_SMEM>>>(ah, al, wph, wpl, bp, out, nullptr, nullptr);
}

// round 6
// speedup vs baseline: 1.1483x; 1.1483x over previous
#include <cuda_runtime.h>
#include <cuda_bf16.h>
#include <cstdint>
#include <cstddef>

#define MBATCH 16
#define LEN    1024
#define EMB    1024
#define NHEAD  8
#define HD     128
#define MROWS  (MBATCH*LEN)   // 16384
#define NHB    (NHEAD*MBATCH) // 128

// ---------------- scratch ----------------
__device__ float g_sk[NHB*LEN];
__device__ float g_sq[NHB*LEN];
__device__ float g_invd[NHB*LEN];
__device__ float g_Vk[NHEAD*EMB];
__device__ float g_Vq[NHEAD*EMB];
__device__ float g_ck[NHEAD];
__device__ float g_cq[NHEAD];
__device__ __nv_bfloat16 g_kh[(size_t)MROWS*EMB];
__device__ __nv_bfloat16 g_kl[(size_t)MROWS*EMB];
__device__ __nv_bfloat16 g_kxh[(size_t)MROWS*EMB];
__device__ __nv_bfloat16 g_kxl[(size_t)MROWS*EMB];
__device__ __nv_bfloat16 g_ah[(size_t)MROWS*EMB];
__device__ __nv_bfloat16 g_al[(size_t)MROWS*EMB];
__device__ __nv_bfloat16 g_Wkh[(size_t)EMB*EMB];
__device__ __nv_bfloat16 g_Wkl[(size_t)EMB*EMB];
__device__ __nv_bfloat16 g_Wph[(size_t)EMB*EMB];
__device__ __nv_bfloat16 g_Wpl[(size_t)EMB*EMB];

// ---------------- helpers ----------------
__device__ __forceinline__ uint32_t smem_u32(const void* p) {
    uint32_t a;
    asm("{ .reg .u64 t; cvta.to.shared.u64 t, %1; cvt.u32.u64 %0, t; }" : "=r"(a) : "l"(p));
    return a;
}
__device__ __forceinline__ void cpa16(uint32_t s, const void* g) {
    asm volatile("cp.async.cg.shared.global [%0], [%1], 16;" :: "r"(s), "l"(g));
}
#define CPA_COMMIT() asm volatile("cp.async.commit_group;" ::: "memory")
#define CPA_WAIT1()  asm volatile("cp.async.wait_group 1;" ::: "memory")

__device__ __forceinline__ void ldsm4(uint32_t* r, uint32_t a) {
    asm volatile("ldmatrix.sync.aligned.m8n8.x4.shared.b16 {%0,%1,%2,%3}, [%4];"
        : "=r"(r[0]), "=r"(r[1]), "=r"(r[2]), "=r"(r[3]) : "r"(a));
}
__device__ __forceinline__ void ldsm4t(uint32_t* r, uint32_t a) {
    asm volatile("ldmatrix.sync.aligned.m8n8.x4.trans.shared.b16 {%0,%1,%2,%3}, [%4];"
        : "=r"(r[0]), "=r"(r[1]), "=r"(r[2]), "=r"(r[3]) : "r"(a));
}
__device__ __forceinline__ void mma_bf16(float* c, const uint32_t* a, const uint32_t* b) {
    asm volatile(
        "mma.sync.aligned.m16n8k16.row.col.f32.bf16.bf16.f32 "
        "{%0,%1,%2,%3}, {%4,%5,%6,%7}, {%8,%9}, {%0,%1,%2,%3};"
        : "+f"(c[0]), "+f"(c[1]), "+f"(c[2]), "+f"(c[3])
        : "r"(a[0]), "r"(a[1]), "r"(a[2]), "r"(a[3]), "r"(b[0]), "r"(b[1]));
}
__device__ __forceinline__ float exp_tanh(float x) {
    float t;
    asm("tanh.approx.f32 %0, %1;" : "=f"(t) : "f"(x));
    return __expf(t);
}
__device__ __forceinline__ uint32_t pack_bf16(float a, float b) {
    __nv_bfloat162 v = {__float2bfloat16(a), __float2bfloat16(b)};
    return *(uint32_t*)&v;
}

// ---------------------------------------------------------------------------
// split fp32 -> bf16 hi + lo.  16 floats/thread, 4 front-batched float4 loads.
// ---------------------------------------------------------------------------
__global__ __launch_bounds__(256) void split_kernel(
    const float* __restrict__ x, __nv_bfloat16* __restrict__ h,
    __nv_bfloat16* __restrict__ l, int n)
{
    int base = (blockIdx.x * 256 + threadIdx.x) * 16;
    if (base >= n) return;
    float4 v[4];
    #pragma unroll
    for (int i = 0; i < 4; i++) v[i] = *(const float4*)(x + base + i * 4);
    #pragma unroll
    for (int i = 0; i < 4; i++) {
        __nv_bfloat16 h0 = __float2bfloat16(v[i].x), h1 = __float2bfloat16(v[i].y);
        __nv_bfloat16 h2 = __float2bfloat16(v[i].z), h3 = __float2bfloat16(v[i].w);
        __nv_bfloat16 l0 = __float2bfloat16(v[i].x - __bfloat162float(h0));
        __nv_bfloat16 l1 = __float2bfloat16(v[i].y - __bfloat162float(h1));
        __nv_bfloat16 l2 = __float2bfloat16(v[i].z - __bfloat162float(h2));
        __nv_bfloat16 l3 = __float2bfloat16(v[i].w - __bfloat162float(h3));
        ((__nv_bfloat162*)(h + base + i * 4))[0] = {h0, h1};
        ((__nv_bfloat162*)(h + base + i * 4))[1] = {h2, h3};
        ((__nv_bfloat162*)(l + base + i * 4))[0] = {l0, l1};
        ((__nv_bfloat162*)(l + base + i * 4))[1] = {l2, l3};
    }
}

// ---------------------------------------------------------------------------
// Vk[h,e] = sum_c Wk[h*128+c, e] * w[c];  ck[h] = sum_c bk[h*128+c]*w[c]
// grid (8 heads, 8 e-chunks), block 256 = 2 c-halves x 128 e-cols.
// ---------------------------------------------------------------------------
__global__ __launch_bounds__(256) void vkq_kernel(
    const float* __restrict__ Wk, const float* __restrict__ bk,
    const float* __restrict__ Wq, const float* __restrict__ bq,
    const float* __restrict__ w)
{
    const int h = blockIdx.x;
    const int tid = threadIdx.x;
    const int half = tid >> 7;          // 0 or 1 (c range)
    const int te = tid & 127;
    const int e = blockIdx.y * 128 + te;
    const int c0 = half * 64;
    const float* rK = Wk + (size_t)(h * HD + c0) * EMB + e;
    const float* rQ = Wq + (size_t)(h * HD + c0) * EMB + e;
    float aK = 0.0f, aQ = 0.0f;
    #pragma unroll 4
    for (int c = 0; c < 64; c++) {
        aK += rK[(size_t)c * EMB] * __ldg(w + c0 + c);
        aQ += rQ[(size_t)c * EMB] * __ldg(w + HD + c0 + c);
    }
    __shared__ float sK[2][128], sQ[2][128];
    sK[half][te] = aK;
    sQ[half][te] = aQ;
    __syncthreads();
    if (tid < 128) {
        g_Vk[h * EMB + e] = sK[0][te] + sK[1][te];
        g_Vq[h * EMB + e] = sQ[0][te] + sQ[1][te];
    }
    if (blockIdx.y == 0 && tid < 128) {
        // warp-free small reduction via shared
        __shared__ float red[128], red2[128];
        red[tid]  = bk[h * HD + tid] * w[tid];
        red2[tid] = bq[h * HD + tid] * w[HD + tid];
        __syncthreads();
        for (int s = 64; s; s >>= 1) {
            if (tid < s) { red[tid] += red[tid + s]; red2[tid] += red2[tid + s]; }
            __syncthreads();
        }
        if (tid == 0) { g_ck[h] = red[0]; g_cq[h] = red2[0]; }
    }
}

// ---------------------------------------------------------------------------
// sk[hb,j] = k[b,j,:]·Vk[h] + ck[h];  sq likewise.  warp per (b,j).
// ---------------------------------------------------------------------------
__global__ __launch_bounds__(256) void sksq_kernel(
    const float* __restrict__ k, const float* __restrict__ q)
{
    const int gw = (blockIdx.x * 256 + threadIdx.x) >> 5;
    const int lane = threadIdx.x & 31;
    const int b = gw >> 10, j = gw & 1023;
    const float* kr = k + (size_t)gw * EMB;
    const float* qr = q + (size_t)gw * EMB;
    float aK[8] = {0,0,0,0,0,0,0,0}, aQ[8] = {0,0,0,0,0,0,0,0};
    for (int t = 0; t < 8; t++) {
        int idx = t*128 + (lane << 2);
        float4 kv = *(const float4*)(kr + idx);
        float4 qv = *(const float4*)(qr + idx);
        #pragma unroll
        for (int h = 0; h < 8; h++) {
            float4 vk = *(const float4*)(g_Vk + h*EMB + idx);
            float4 vq = *(const float4*)(g_Vq + h*EMB + idx);
            aK[h] += kv.x*vk.x + kv.y*vk.y + kv.z*vk.z + kv.w*vk.w;
            aQ[h] += qv.x*vq.x + qv.y*vq.y + qv.z*vq.z + qv.w*vq.w;
        }
    }
    #pragma unroll
    for (int h = 0; h < 8; h++)
        #pragma unroll
        for (int o = 16; o; o >>= 1) {
            aK[h] += __shfl_xor_sync(0xffffffffu, aK[h], o);
            aQ[h] += __shfl_xor_sync(0xffffffffu, aQ[h], o);
        }
    if (lane < 8) {
        int h = lane;
        g_sk[(size_t)(h*MBATCH + b)*LEN + j] = aK[h] + g_ck[h];
        g_sq[(size_t)(h*MBATCH + b)*LEN + j] = aQ[h] + g_cq[h];
    }
}

// ---------------------------------------------------------------------------
// inv_d[hb,i] = 1 / sum_j exp(tanh(sq_i + sk_j))
// ---------------------------------------------------------------------------
__global__ __launch_bounds__(128) void denom_kernel()
{
    __shared__ float sks[LEN];
    const int hb = blockIdx.x >> 3;
    const int i0 = (blockIdx.x & 7) << 7;
    for (int t = threadIdx.x; t < LEN; t += 128) sks[t] = g_sk[hb * LEN + t];
    __syncthreads();
    const int i = i0 + threadIdx.x;
    const float sqi = g_sq[hb * LEN + i];
    float s = 0.0f;
    #pragma unroll 8
    for (int j = 0; j < LEN; j++) s += exp_tanh(sqi + sks[j]);
    g_invd[hb * LEN + i] = __fdividef(1.0f, s);
}

// ---------------------------------------------------------------------------
// mma.sync split-bf16 GEMM, 2-stage cp.async pipeline (round-4 schedule).
// ---------------------------------------------------------------------------
#define PADROW  40
#define PLANE_B (128*PADROW*2)
#define OFF_AH  0
#define OFF_AL  (PLANE_B)
#define OFF_BH  (2*PLANE_B)
#define OFF_BL  (3*PLANE_B)
#define BUF_B   (4*PLANE_B)
#define GEMM_SMEM (2*BUF_B)
#define NCH     32

__global__ __launch_bounds__(256) void gemm_mma(
    const __nv_bfloat16* __restrict__ Ah, const __nv_bfloat16* __restrict__ Al,
    const __nv_bfloat16* __restrict__ Bh, const __nv_bfloat16* __restrict__ Bl,
    const float* __restrict__ bias, float* __restrict__ C,
    __nv_bfloat16* __restrict__ Ch, __nv_bfloat16* __restrict__ Cl)
{
    extern __shared__ char smem[];
    const uint32_t sb = smem_u32(smem);
    const int tid = threadIdx.x;
    const int wid = tid >> 5, lane = tid & 31;
    const int g = lane >> 2, tig = lane & 3;
    const int m0 = blockIdx.y << 7, n0 = blockIdx.x << 7;
    const int wm = (wid & 1) << 6;
    const int wn = (wid >> 1) << 5;
    const uint32_t lrow = lane & 15, lhalf = (lane >> 4) * 16;

    const int lr = tid >> 1;
    const int lc = (tid & 1) * 2;
    const uint32_t s_off = lr * 80 + lc * 16;
    const __nv_bfloat16* gAh = Ah + (size_t)(m0 + lr) * 1024 + lc * 8;
    const __nv_bfloat16* gAl = Al + (size_t)(m0 + lr) * 1024 + lc * 8;
    const __nv_bfloat16* gBh = Bh + (size_t)(n0 + lr) * 1024 + lc * 8;
    const __nv_bfloat16* gBl = Bl + (size_t)(n0 + lr) * 1024 + lc * 8;

    float acc[4][4][4];
    #pragma unroll
    for (int i = 0; i < 4; i++)
        #pragma unroll
        for (int j = 0; j < 4; j++)
            #pragma unroll
            for (int r = 0; r < 4; r++) acc[i][j][r] = 0.0f;

    #pragma unroll
    for (int pc = 0; pc < 2; pc++) {
        uint32_t d = sb + pc * BUF_B + s_off;
        size_t gk = (size_t)pc * 32;
        cpa16(d + OFF_AH, gAh + gk);      cpa16(d + OFF_AH + 16, gAh + gk + 8);
        cpa16(d + OFF_AL, gAl + gk);      cpa16(d + OFF_AL + 16, gAl + gk + 8);
        cpa16(d + OFF_BH, gBh + gk);      cpa16(d + OFF_BH + 16, gBh + gk + 8);
        cpa16(d + OFF_BL, gBl + gk);      cpa16(d + OFF_BL + 16, gBl + gk + 8);
        CPA_COMMIT();
    }

    for (int c = 0; c < NCH; c++) {
        const int buf = c & 1;
        CPA_WAIT1();
        __syncthreads();

        const uint32_t bp = sb + buf * BUF_B;
        #pragma unroll
        for (int ks = 0; ks < 2; ks++) {
            const uint32_t kb = ks * 32;
            uint32_t ah[4][4], al[4][4], bh[4][2], bl[4][2];
            #pragma unroll
            for (int mf = 0; mf < 4; mf++) {
                uint32_t ra = bp + (wm + mf*16 + lrow) * 80 + kb + lhalf;
                ldsm4(ah[mf], ra + OFF_AH);
                ldsm4(al[mf], ra + OFF_AL);
            }
            #pragma unroll
            for (int nh = 0; nh < 2; nh++) {
                uint32_t rb = bp + (wn + nh*16 + lrow) * 80 + kb + lhalf;
                uint32_t t[4];
                ldsm4(t, rb + OFF_BH);
                bh[nh*2][0] = t[0]; bh[nh*2][1] = t[2];
                bh[nh*2+1][0] = t[1]; bh[nh*2+1][1] = t[3];
                ldsm4(t, rb + OFF_BL);
                bl[nh*2][0] = t[0]; bl[nh*2][1] = t[2];
                bl[nh*2+1][0] = t[1]; bl[nh*2+1][1] = t[3];
            }
            #pragma unroll
            for (int mf = 0; mf < 4; mf++)
                #pragma unroll
                for (int nf = 0; nf < 4; nf++) {
                    mma_bf16(acc[mf][nf], ah[mf], bh[nf]);
                    mma_bf16(acc[mf][nf], ah[mf], bl[nf]);
                    mma_bf16(acc[mf][nf], al[mf], bh[nf]);
                }
        }
        __syncthreads();
        if (c + 2 < NCH) {
            uint32_t d = sb + buf * BUF_B + s_off;
            size_t gk = (size_t)(c + 2) * 32;
            cpa16(d + OFF_AH, gAh + gk);      cpa16(d + OFF_AH + 16, gAh + gk + 8);
            cpa16(d + OFF_AL, gAl + gk);      cpa16(d + OFF_AL + 16, gAl + gk + 8);
            cpa16(d + OFF_BH, gBh + gk);      cpa16(d + OFF_BH + 16, gBh + gk + 8);
            cpa16(d + OFF_BL, gBl + gk);      cpa16(d + OFF_BL + 16, gBl + gk + 8);
        }
        CPA_COMMIT();
    }

    #pragma unroll
    for (int mf = 0; mf < 4; mf++) {
        #pragma unroll
        for (int nf = 0; nf < 4; nf++) {
            const int row = m0 + wm + mf * 16 + g;
            const int col = n0 + wn + nf * 8 + 2 * tig;
            const float b0 = bias[col], b1 = bias[col + 1];
            float v00 = acc[mf][nf][0] + b0, v01 = acc[mf][nf][1] + b1;
            float v10 = acc[mf][nf][2] + b0, v11 = acc[mf][nf][3] + b1;
            if (C) {
                *(float2*)(C + (size_t)row * 1024 + col) = {v00, v01};
                *(float2*)(C + (size_t)(row + 8) * 1024 + col) = {v10, v11};
            }
            if (Ch) {
                uint32_t h0 = pack_bf16(v00, v01), h1 = pack_bf16(v10, v11);
                float r00 = v00 - __bfloat162float(__float2bfloat16(v00));
                float r01 = v01 - __bfloat162float(__float2bfloat16(v01));
                float r10 = v10 - __bfloat162float(__float2bfloat16(v10));
                float r11 = v11 - __bfloat162float(__float2bfloat16(v11));
                *(uint32_t*)(Ch + (size_t)row * 1024 + col) = h0;
                *(uint32_t*)(Ch + (size_t)(row + 8) * 1024 + col) = h1;
                *(uint32_t*)(Cl + (size_t)row * 1024 + col) = pack_bf16(r00, r01);
                *(uint32_t*)(Cl + (size_t)(row + 8) * 1024 + col) = pack_bf16(r10, r11);
            }
        }
    }
}

// ---------------------------------------------------------------------------
// Fused attention, 2-stage pipeline (round-4 schedule).
// ---------------------------------------------------------------------------
#define A_SK   0
#define A_SQ   4096
#define A_ID   4608
#define A_ST   5120
#define A_PH   0
#define A_PL   10240
#define A_KH   20480
#define A_KL   29184
#define A_STB  37888
#define ATTN_SMEM (A_ST + 2*A_STB)

__global__ __launch_bounds__(256) void attn_mma(
    const __nv_bfloat16* __restrict__ kxh, const __nv_bfloat16* __restrict__ kxl,
    float* __restrict__ score,
    __nv_bfloat16* __restrict__ aout_h, __nv_bfloat16* __restrict__ aout_l)
{
    extern __shared__ char smem[];
    const uint32_t sb = smem_u32(smem);
    float* sksA = (float*)smem;
    float* sqsA = (float*)(smem + A_SQ);
    float* idsA = (float*)(smem + A_ID);

    const int tid = threadIdx.x;
    const int wid = tid >> 5, lane = tid & 31;
    const int g = lane >> 2, tig = lane & 3;
    const int hb = blockIdx.y;
    const int h = hb >> 4, b = hb & 15;
    const int i0 = blockIdx.x << 7;
    const int wm = (wid & 1) << 6;
    const int wn = (wid >> 1) << 5;
    const uint32_t lrow = lane & 15, lhalf = (lane >> 4) * 16;

    for (int t = tid; t < LEN; t += 256) sksA[t] = g_sk[hb * LEN + t];
    if (tid < 128) {
        sqsA[tid] = g_sq[hb * LEN + i0 + tid];
        idsA[tid] = g_invd[hb * LEN + i0 + tid];
    }
    __syncthreads();

    const int prow = tid >> 1;
    const int pj0 = (tid & 1) * 16;
    const float sqi = sqsA[prow];
    const float idi = idsA[prow];
    float* srow = score + ((size_t)hb * LEN + i0 + prow) * LEN + pj0;
    const uint32_t p_off = prow * 80 + pj0 * 2;

    const int krow = tid >> 3;
    const int kseg = tid & 7;
    const __nv_bfloat16* gKh = kxh + (size_t)(b * 1024 + krow) * 1024 + h * 128 + kseg * 8;
    const __nv_bfloat16* gKl = kxl + (size_t)(b * 1024 + krow) * 1024 + h * 128 + kseg * 8;
    const uint32_t k_off = krow * 272 + kseg * 16;

    float acc[4][4][4];
    #pragma unroll
    for (int i = 0; i < 4; i++)
        #pragma unroll
        for (int j = 0; j < 4; j++)
            #pragma unroll
            for (int r = 0; r < 4; r++) acc[i][j][r] = 0.0f;

    #define GEN_CHUNK(ch, stbase) do {                                          \
        const int jb = (ch) * 32;                                               \
        float pf[16]; uint32_t hp[8], lp[8];                                    \
        _Pragma("unroll")                                                       \
        for (int u = 0; u < 16; u++)                                            \
            pf[u] = exp_tanh(sqi + sksA[jb + pj0 + u]) * idi;                   \
        _Pragma("unroll")                                                       \
        for (int u = 0; u < 8; u++) {                                           \
            float p0 = pf[2*u], p1 = pf[2*u+1];                                 \
            hp[u] = pack_bf16(p0, p1);                                          \
            float r0 = p0 - __bfloat162float(__float2bfloat16(p0));             \
            float r1 = p1 - __bfloat162float(__float2bfloat16(p1));             \
            lp[u] = pack_bf16(r0, r1);                                          \
        }                                                                       \
        *(float4*)(srow + jb)      = {pf[0], pf[1], pf[2], pf[3]};              \
        *(float4*)(srow + jb + 4)  = {pf[4], pf[5], pf[6], pf[7]};              \
        *(float4*)(srow + jb + 8)  = {pf[8], pf[9], pf[10], pf[11]};            \
        *(float4*)(srow + jb + 12) = {pf[12], pf[13], pf[14], pf[15]};          \
        asm volatile("st.shared.v4.b32 [%0], {%1,%2,%3,%4};" ::                 \
            "r"((stbase) + A_PH + p_off), "r"(hp[0]), "r"(hp[1]), "r"(hp[2]), "r"(hp[3]) : "memory"); \
        asm volatile("st.shared.v4.b32 [%0], {%1,%2,%3,%4};" ::                 \
            "r"((stbase) + A_PH + p_off + 16), "r"(hp[4]), "r"(hp[5]), "r"(hp[6]), "r"(hp[7]) : "memory"); \
        asm volatile("st.shared.v4.b32 [%0], {%1,%2,%3,%4};" ::                 \
            "r"((stbase) + A_PL + p_off), "r"(lp[0]), "r"(lp[1]), "r"(lp[2]), "r"(lp[3]) : "memory"); \
        asm volatile("st.shared.v4.b32 [%0], {%1,%2,%3,%4};" ::                 \
            "r"((stbase) + A_PL + p_off + 16), "r"(lp[4]), "r"(lp[5]), "r"(lp[6]), "r"(lp[7]) : "memory"); \
        const size_t gkoff = (size_t)jb * 1024;                                 \
        cpa16((stbase) + A_KH + k_off,       gKh + gkoff);                      \
        cpa16((stbase) + A_KH + k_off + 128, gKh + gkoff + 64);                 \
        cpa16((stbase) + A_KL + k_off,       gKl + gkoff);                      \
        cpa16((stbase) + A_KL + k_off + 128, gKl + gkoff + 64);                 \
    } while (0)

    GEN_CHUNK(0, sb + A_ST);
    CPA_COMMIT();
    GEN_CHUNK(1, sb + A_ST + A_STB);
    CPA_COMMIT();
    CPA_WAIT1();
    __syncthreads();

    for (int c = 0; c < 32; c++) {
        const uint32_t stb = sb + A_ST + (c & 1) * A_STB;
        #pragma unroll
        for (int ks = 0; ks < 2; ks++) {
            const uint32_t kb = ks * 32;
            uint32_t ph[4][4], pl[4][4], bh[4][2], bl[4][2];
            #pragma unroll
            for (int mf = 0; mf < 4; mf++) {
                uint32_t ra = stb + (wm + mf*16 + lrow) * 80 + kb + lhalf;
                ldsm4(ph[mf], ra + A_PH);
                ldsm4(pl[mf], ra + A_PL);
            }
            #pragma unroll
            for (int nh = 0; nh < 2; nh++) {
                uint32_t rb = stb + (ks*16 + lrow) * 272 + (wn + nh*16) * 2 + lhalf;
                uint32_t t[4];
                ldsm4t(t, rb + A_KH);
                bh[nh*2][0] = t[0]; bh[nh*2][1] = t[1];
                bh[nh*2+1][0] = t[2]; bh[nh*2+1][1] = t[3];
                ldsm4t(t, rb + A_KL);
                bl[nh*2][0] = t[0]; bl[nh*2][1] = t[1];
                bl[nh*2+1][0] = t[2]; bl[nh*2+1][1] = t[3];
            }
            #pragma unroll
            for (int mf = 0; mf < 4; mf++)
                #pragma unroll
                for (int nf = 0; nf < 4; nf++) {
                    mma_bf16(acc[mf][nf], ph[mf], bh[nf]);
                    mma_bf16(acc[mf][nf], ph[mf], bl[nf]);
                    mma_bf16(acc[mf][nf], pl[mf], bh[nf]);
                }
        }
        __syncthreads();
        if (c + 2 < 32) GEN_CHUNK(c + 2, stb);
        CPA_COMMIT();
        CPA_WAIT1();
        __syncthreads();
    }

    #pragma unroll
    for (int mf = 0; mf < 4; mf++) {
        #pragma unroll
        for (int nf = 0; nf < 4; nf++) {
            const int r0 = wm + mf * 16 + g;
            const int col = wn + nf * 8 + 2 * tig;
            float v00 = acc[mf][nf][0], v01 = acc[mf][nf][1];
            float v10 = acc[mf][nf][2], v11 = acc[mf][nf][3];
            size_t o0 = (size_t)(b * 1024 + i0 + r0) * 1024 + h * 128 + col;
            size_t o1 = (size_t)(b * 1024 + i0 + r0 + 8) * 1024 + h * 128 + col;
            *(uint32_t*)(aout_h + o0) = pack_bf16(v00, v01);
            *(uint32_t*)(aout_h + o1) = pack_bf16(v10, v11);
            float r00 = v00 - __bfloat162float(__float2bfloat16(v00));
            float r01 = v01 - __bfloat162float(__float2bfloat16(v01));
            float r10 = v10 - __bfloat162float(__float2bfloat16(v10));
            float r11 = v11 - __bfloat162float(__float2bfloat16(v11));
            *(uint32_t*)(aout_l + o0) = pack_bf16(r00, r01);
            *(uint32_t*)(aout_l + o1) = pack_bf16(r10, r11);
        }
    }
}

// ---------------------------------------------------------------------------
extern "C" void kernel_launch(void* const* d_in, const int* in_sizes, int n_in,
                              void* d_out, int out_size)
{
    const float* k  = (const float*)d_in[0];
    const float* q  = (const float*)d_in[1];
    const float* Wk = (const float*)d_in[2];
    const float* bk = (const float*)d_in[3];
    const float* Wq = (const float*)d_in[4];
    const float* bq = (const float*)d_in[5];
    const float* w  = (const float*)d_in[6];
    const float* Wp = (const float*)d_in[7];
    const float* bp = (const float*)d_in[8];
    float* out   = (float*)d_out;
    float* score = out + (size_t)MROWS * EMB;

    __nv_bfloat16 *kh,*kl,*kxh,*kxl,*ah,*al,*wkh,*wkl,*wph,*wpl;
    cudaGetSymbolAddress((void**)&kh,  g_kh);   cudaGetSymbolAddress((void**)&kl,  g_kl);
    cudaGetSymbolAddress((void**)&kxh, g_kxh);  cudaGetSymbolAddress((void**)&kxl, g_kxl);
    cudaGetSymbolAddress((void**)&ah,  g_ah);   cudaGetSymbolAddress((void**)&al,  g_al);
    cudaGetSymbolAddress((void**)&wkh, g_Wkh);  cudaGetSymbolAddress((void**)&wkl, g_Wkl);
    cudaGetSymbolAddress((void**)&wph, g_Wph);  cudaGetSymbolAddress((void**)&wpl, g_Wpl);

    cudaFuncSetAttribute(gemm_mma, cudaFuncAttributeMaxDynamicSharedMemorySize, GEMM_SMEM);
    cudaFuncSetAttribute(attn_mma, cudaFuncAttributeMaxDynamicSharedMemorySize, ATTN_SMEM);

    const int nBig = MROWS * EMB;
    const int nW   = EMB * EMB;
    split_kernel<<<nBig/16/256, 256>>>(k, kh, kl, nBig);
    split_kernel<<<nW/16/256, 256>>>(Wk, wkh, wkl, nW);
    split_kernel<<<nW/16/256, 256>>>(Wp, wph, wpl, nW);

    vkq_kernel<<<dim3(NHEAD, 8), 256>>>(Wk, bk, Wq, bq, w);
    sksq_kernel<<<MROWS/8, 256>>>(k, q);
    denom_kernel<<<NHB * 8, 128>>>();

    dim3 gg(EMB / 128, MROWS / 128);
    gemm_mma<<<gg, 256, GEMM_SMEM>>>(kh, kl, wkh, wkl, bk, nullptr, kxh, kxl);
    attn_mma<<<dim3(8, NHB), 256, ATTN_SMEM>>>(kxh, kxl, score, ah, al);
    gemm_mma<<<gg, 256, GEMM_SMEM>>>(ah, al, wph, wpl, bp, out, nullptr, nullptr);
}

// round 7
// speedup vs baseline: 1.1543x; 1.0052x over previous
#include <cuda_runtime.h>
#include <cuda_bf16.h>
#include <cstdint>
#include <cstddef>

#define MBATCH 16
#define LEN    1024
#define EMB    1024
#define NHEAD  8
#define HD     128
#define MROWS  (MBATCH*LEN)   // 16384
#define NHB    (NHEAD*MBATCH) // 128

// ---------------- scratch ----------------
__device__ float g_sk[NHB*LEN];
__device__ float g_sq[NHB*LEN];
__device__ float g_invd[NHB*LEN];
__device__ float g_Vk[NHEAD*EMB];
__device__ float g_Vq[NHEAD*EMB];
__device__ float g_ck[NHEAD];
__device__ float g_cq[NHEAD];
__device__ __nv_bfloat16 g_kh[(size_t)MROWS*EMB];
__device__ __nv_bfloat16 g_kl[(size_t)MROWS*EMB];
__device__ __nv_bfloat16 g_kxh[(size_t)MROWS*EMB];
__device__ __nv_bfloat16 g_kxl[(size_t)MROWS*EMB];
__device__ __nv_bfloat16 g_ah[(size_t)MROWS*EMB];
__device__ __nv_bfloat16 g_al[(size_t)MROWS*EMB];
__device__ __nv_bfloat16 g_Wkh[(size_t)EMB*EMB];
__device__ __nv_bfloat16 g_Wkl[(size_t)EMB*EMB];
__device__ __nv_bfloat16 g_Wph[(size_t)EMB*EMB];
__device__ __nv_bfloat16 g_Wpl[(size_t)EMB*EMB];

// ---------------- helpers ----------------
__device__ __forceinline__ uint32_t smem_u32(const void* p) {
    uint32_t a;
    asm("{ .reg .u64 t; cvta.to.shared.u64 t, %1; cvt.u32.u64 %0, t; }" : "=r"(a) : "l"(p));
    return a;
}
__device__ __forceinline__ void cpa16(uint32_t s, const void* g) {
    asm volatile("cp.async.cg.shared.global [%0], [%1], 16;" :: "r"(s), "l"(g));
}
#define CPA_COMMIT() asm volatile("cp.async.commit_group;" ::: "memory")
#define CPA_WAIT1()  asm volatile("cp.async.wait_group 1;" ::: "memory")

__device__ __forceinline__ void ldsm4(uint32_t* r, uint32_t a) {
    asm volatile("ldmatrix.sync.aligned.m8n8.x4.shared.b16 {%0,%1,%2,%3}, [%4];"
        : "=r"(r[0]), "=r"(r[1]), "=r"(r[2]), "=r"(r[3]) : "r"(a));
}
__device__ __forceinline__ void ldsm4t(uint32_t* r, uint32_t a) {
    asm volatile("ldmatrix.sync.aligned.m8n8.x4.trans.shared.b16 {%0,%1,%2,%3}, [%4];"
        : "=r"(r[0]), "=r"(r[1]), "=r"(r[2]), "=r"(r[3]) : "r"(a));
}
__device__ __forceinline__ void mma_bf16(float* c, const uint32_t* a, const uint32_t* b) {
    asm volatile(
        "mma.sync.aligned.m16n8k16.row.col.f32.bf16.bf16.f32 "
        "{%0,%1,%2,%3}, {%4,%5,%6,%7}, {%8,%9}, {%0,%1,%2,%3};"
        : "+f"(c[0]), "+f"(c[1]), "+f"(c[2]), "+f"(c[3])
        : "r"(a[0]), "r"(a[1]), "r"(a[2]), "r"(a[3]), "r"(b[0]), "r"(b[1]));
}
__device__ __forceinline__ float exp_tanh(float x) {
    float t;
    asm("tanh.approx.f32 %0, %1;" : "=f"(t) : "f"(x));
    return __expf(t);
}
__device__ __forceinline__ uint32_t pack_bf16(float a, float b) {
    __nv_bfloat162 v = {__float2bfloat16(a), __float2bfloat16(b)};
    return *(uint32_t*)&v;
}

// ---------------------------------------------------------------------------
// split fp32 -> bf16 hi + lo.  16 floats/thread, 4 front-batched float4 loads.
// ---------------------------------------------------------------------------
__global__ __launch_bounds__(256) void split_kernel(
    const float* __restrict__ x, __nv_bfloat16* __restrict__ h,
    __nv_bfloat16* __restrict__ l, int n)
{
    int base = (blockIdx.x * 256 + threadIdx.x) * 16;
    if (base >= n) return;
    float4 v[4];
    #pragma unroll
    for (int i = 0; i < 4; i++) v[i] = *(const float4*)(x + base + i * 4);
    #pragma unroll
    for (int i = 0; i < 4; i++) {
        __nv_bfloat16 h0 = __float2bfloat16(v[i].x), h1 = __float2bfloat16(v[i].y);
        __nv_bfloat16 h2 = __float2bfloat16(v[i].z), h3 = __float2bfloat16(v[i].w);
        __nv_bfloat16 l0 = __float2bfloat16(v[i].x - __bfloat162float(h0));
        __nv_bfloat16 l1 = __float2bfloat16(v[i].y - __bfloat162float(h1));
        __nv_bfloat16 l2 = __float2bfloat16(v[i].z - __bfloat162float(h2));
        __nv_bfloat16 l3 = __float2bfloat16(v[i].w - __bfloat162float(h3));
        ((__nv_bfloat162*)(h + base + i * 4))[0] = {h0, h1};
        ((__nv_bfloat162*)(h + base + i * 4))[1] = {h2, h3};
        ((__nv_bfloat162*)(l + base + i * 4))[0] = {l0, l1};
        ((__nv_bfloat162*)(l + base + i * 4))[1] = {l2, l3};
    }
}

// ---------------------------------------------------------------------------
// Vk[h,e] = sum_c Wk[h*128+c, e] * w[c];  ck[h] = sum_c bk[h*128+c]*w[c]
// grid (8 heads, 16 e-chunks), block 256 = 4 c-quarters x 64 e-cols.
// ---------------------------------------------------------------------------
__global__ __launch_bounds__(256) void vkq_kernel(
    const float* __restrict__ Wk, const float* __restrict__ bk,
    const float* __restrict__ Wq, const float* __restrict__ bq,
    const float* __restrict__ w)
{
    const int h = blockIdx.x;
    const int tid = threadIdx.x;
    const int quarter = tid >> 6;       // 0..3 (c range)
    const int te = tid & 63;
    const int e = blockIdx.y * 64 + te;
    const int c0 = quarter * 32;
    const float* rK = Wk + (size_t)(h * HD + c0) * EMB + e;
    const float* rQ = Wq + (size_t)(h * HD + c0) * EMB + e;
    float aK = 0.0f, aQ = 0.0f;
    #pragma unroll 4
    for (int c = 0; c < 32; c++) {
        aK += rK[(size_t)c * EMB] * __ldg(w + c0 + c);
        aQ += rQ[(size_t)c * EMB] * __ldg(w + HD + c0 + c);
    }
    __shared__ float sK[4][64], sQ[4][64];
    sK[quarter][te] = aK;
    sQ[quarter][te] = aQ;
    __syncthreads();
    if (tid < 64) {
        g_Vk[h * EMB + e] = sK[0][te] + sK[1][te] + sK[2][te] + sK[3][te];
        g_Vq[h * EMB + e] = sQ[0][te] + sQ[1][te] + sQ[2][te] + sQ[3][te];
    }
    if (blockIdx.y == 0 && tid < 128) {
        __shared__ float red[128], red2[128];
        red[tid]  = bk[h * HD + tid] * w[tid];
        red2[tid] = bq[h * HD + tid] * w[HD + tid];
        __syncthreads();
        for (int s = 64; s; s >>= 1) {
            if (tid < s) { red[tid] += red[tid + s]; red2[tid] += red2[tid + s]; }
            __syncthreads();
        }
        if (tid == 0) { g_ck[h] = red[0]; g_cq[h] = red2[0]; }
    }
}

// ---------------------------------------------------------------------------
// sk[hb,j] = k[b,j,:]·Vk[h] + ck[h];  sq likewise.  warp per (b,j).
// ---------------------------------------------------------------------------
__global__ __launch_bounds__(256) void sksq_kernel(
    const float* __restrict__ k, const float* __restrict__ q)
{
    const int gw = (blockIdx.x * 256 + threadIdx.x) >> 5;
    const int lane = threadIdx.x & 31;
    const int b = gw >> 10, j = gw & 1023;
    const float* kr = k + (size_t)gw * EMB;
    const float* qr = q + (size_t)gw * EMB;
    float aK[8] = {0,0,0,0,0,0,0,0}, aQ[8] = {0,0,0,0,0,0,0,0};
    for (int t = 0; t < 8; t++) {
        int idx = t*128 + (lane << 2);
        float4 kv = *(const float4*)(kr + idx);
        float4 qv = *(const float4*)(qr + idx);
        #pragma unroll
        for (int h = 0; h < 8; h++) {
            float4 vk = *(const float4*)(g_Vk + h*EMB + idx);
            float4 vq = *(const float4*)(g_Vq + h*EMB + idx);
            aK[h] += kv.x*vk.x + kv.y*vk.y + kv.z*vk.z + kv.w*vk.w;
            aQ[h] += qv.x*vq.x + qv.y*vq.y + qv.z*vq.z + qv.w*vq.w;
        }
    }
    #pragma unroll
    for (int h = 0; h < 8; h++)
        #pragma unroll
        for (int o = 16; o; o >>= 1) {
            aK[h] += __shfl_xor_sync(0xffffffffu, aK[h], o);
            aQ[h] += __shfl_xor_sync(0xffffffffu, aQ[h], o);
        }
    if (lane < 8) {
        int h = lane;
        g_sk[(size_t)(h*MBATCH + b)*LEN + j] = aK[h] + g_ck[h];
        g_sq[(size_t)(h*MBATCH + b)*LEN + j] = aQ[h] + g_cq[h];
    }
}

// ---------------------------------------------------------------------------
// inv_d[hb,i] = 1 / sum_j exp(tanh(sq_i + sk_j))
// ---------------------------------------------------------------------------
__global__ __launch_bounds__(128) void denom_kernel()
{
    __shared__ float sks[LEN];
    const int hb = blockIdx.x >> 3;
    const int i0 = (blockIdx.x & 7) << 7;
    for (int t = threadIdx.x; t < LEN; t += 128) sks[t] = g_sk[hb * LEN + t];
    __syncthreads();
    const int i = i0 + threadIdx.x;
    const float sqi = g_sq[hb * LEN + i];
    float s = 0.0f;
    #pragma unroll 8
    for (int j = 0; j < LEN; j++) s += exp_tanh(sqi + sks[j]);
    g_invd[hb * LEN + i] = __fdividef(1.0f, s);
}

// ---------------------------------------------------------------------------
// mma.sync split-bf16 GEMM, 2-stage cp.async pipeline.
// __launch_bounds__(256,2): force 128 regs -> 2 CTAs/SM (occupancy experiment)
// ---------------------------------------------------------------------------
#define PADROW  40
#define PLANE_B (128*PADROW*2)
#define OFF_AH  0
#define OFF_AL  (PLANE_B)
#define OFF_BH  (2*PLANE_B)
#define OFF_BL  (3*PLANE_B)
#define BUF_B   (4*PLANE_B)
#define GEMM_SMEM (2*BUF_B)
#define NCH     32

__global__ __launch_bounds__(256, 2) void gemm_mma(
    const __nv_bfloat16* __restrict__ Ah, const __nv_bfloat16* __restrict__ Al,
    const __nv_bfloat16* __restrict__ Bh, const __nv_bfloat16* __restrict__ Bl,
    const float* __restrict__ bias, float* __restrict__ C,
    __nv_bfloat16* __restrict__ Ch, __nv_bfloat16* __restrict__ Cl)
{
    extern __shared__ char smem[];
    const uint32_t sb = smem_u32(smem);
    const int tid = threadIdx.x;
    const int wid = tid >> 5, lane = tid & 31;
    const int g = lane >> 2, tig = lane & 3;
    const int m0 = blockIdx.y << 7, n0 = blockIdx.x << 7;
    const int wm = (wid & 1) << 6;
    const int wn = (wid >> 1) << 5;
    const uint32_t lrow = lane & 15, lhalf = (lane >> 4) * 16;

    const int lr = tid >> 1;
    const int lc = (tid & 1) * 2;
    const uint32_t s_off = lr * 80 + lc * 16;
    const __nv_bfloat16* gAh = Ah + (size_t)(m0 + lr) * 1024 + lc * 8;
    const __nv_bfloat16* gAl = Al + (size_t)(m0 + lr) * 1024 + lc * 8;
    const __nv_bfloat16* gBh = Bh + (size_t)(n0 + lr) * 1024 + lc * 8;
    const __nv_bfloat16* gBl = Bl + (size_t)(n0 + lr) * 1024 + lc * 8;

    float acc[4][4][4];
    #pragma unroll
    for (int i = 0; i < 4; i++)
        #pragma unroll
        for (int j = 0; j < 4; j++)
            #pragma unroll
            for (int r = 0; r < 4; r++) acc[i][j][r] = 0.0f;

    #pragma unroll
    for (int pc = 0; pc < 2; pc++) {
        uint32_t d = sb + pc * BUF_B + s_off;
        size_t gk = (size_t)pc * 32;
        cpa16(d + OFF_AH, gAh + gk);      cpa16(d + OFF_AH + 16, gAh + gk + 8);
        cpa16(d + OFF_AL, gAl + gk);      cpa16(d + OFF_AL + 16, gAl + gk + 8);
        cpa16(d + OFF_BH, gBh + gk);      cpa16(d + OFF_BH + 16, gBh + gk + 8);
        cpa16(d + OFF_BL, gBl + gk);      cpa16(d + OFF_BL + 16, gBl + gk + 8);
        CPA_COMMIT();
    }

    for (int c = 0; c < NCH; c++) {
        const int buf = c & 1;
        CPA_WAIT1();
        __syncthreads();

        const uint32_t bp = sb + buf * BUF_B;
        #pragma unroll
        for (int ks = 0; ks < 2; ks++) {
            const uint32_t kb = ks * 32;
            uint32_t ah[4][4], al[4][4], bh[4][2], bl[4][2];
            #pragma unroll
            for (int mf = 0; mf < 4; mf++) {
                uint32_t ra = bp + (wm + mf*16 + lrow) * 80 + kb + lhalf;
                ldsm4(ah[mf], ra + OFF_AH);
                ldsm4(al[mf], ra + OFF_AL);
            }
            #pragma unroll
            for (int nh = 0; nh < 2; nh++) {
                uint32_t rb = bp + (wn + nh*16 + lrow) * 80 + kb + lhalf;
                uint32_t t[4];
                ldsm4(t, rb + OFF_BH);
                bh[nh*2][0] = t[0]; bh[nh*2][1] = t[2];
                bh[nh*2+1][0] = t[1]; bh[nh*2+1][1] = t[3];
                ldsm4(t, rb + OFF_BL);
                bl[nh*2][0] = t[0]; bl[nh*2][1] = t[2];
                bl[nh*2+1][0] = t[1]; bl[nh*2+1][1] = t[3];
            }
            #pragma unroll
            for (int mf = 0; mf < 4; mf++)
                #pragma unroll
                for (int nf = 0; nf < 4; nf++) {
                    mma_bf16(acc[mf][nf], ah[mf], bh[nf]);
                    mma_bf16(acc[mf][nf], ah[mf], bl[nf]);
                    mma_bf16(acc[mf][nf], al[mf], bh[nf]);
                }
        }
        __syncthreads();
        if (c + 2 < NCH) {
            uint32_t d = sb + buf * BUF_B + s_off;
            size_t gk = (size_t)(c + 2) * 32;
            cpa16(d + OFF_AH, gAh + gk);      cpa16(d + OFF_AH + 16, gAh + gk + 8);
            cpa16(d + OFF_AL, gAl + gk);      cpa16(d + OFF_AL + 16, gAl + gk + 8);
            cpa16(d + OFF_BH, gBh + gk);      cpa16(d + OFF_BH + 16, gBh + gk + 8);
            cpa16(d + OFF_BL, gBl + gk);      cpa16(d + OFF_BL + 16, gBl + gk + 8);
        }
        CPA_COMMIT();
    }

    #pragma unroll
    for (int mf = 0; mf < 4; mf++) {
        #pragma unroll
        for (int nf = 0; nf < 4; nf++) {
            const int row = m0 + wm + mf * 16 + g;
            const int col = n0 + wn + nf * 8 + 2 * tig;
            const float b0 = bias[col], b1 = bias[col + 1];
            float v00 = acc[mf][nf][0] + b0, v01 = acc[mf][nf][1] + b1;
            float v10 = acc[mf][nf][2] + b0, v11 = acc[mf][nf][3] + b1;
            if (C) {
                *(float2*)(C + (size_t)row * 1024 + col) = {v00, v01};
                *(float2*)(C + (size_t)(row + 8) * 1024 + col) = {v10, v11};
            }
            if (Ch) {
                uint32_t h0 = pack_bf16(v00, v01), h1 = pack_bf16(v10, v11);
                float r00 = v00 - __bfloat162float(__float2bfloat16(v00));
                float r01 = v01 - __bfloat162float(__float2bfloat16(v01));
                float r10 = v10 - __bfloat162float(__float2bfloat16(v10));
                float r11 = v11 - __bfloat162float(__float2bfloat16(v11));
                *(uint32_t*)(Ch + (size_t)row * 1024 + col) = h0;
                *(uint32_t*)(Ch + (size_t)(row + 8) * 1024 + col) = h1;
                *(uint32_t*)(Cl + (size_t)row * 1024 + col) = pack_bf16(r00, r01);
                *(uint32_t*)(Cl + (size_t)(row + 8) * 1024 + col) = pack_bf16(r10, r11);
            }
        }
    }
}

// ---------------------------------------------------------------------------
// Fused attention, 2-stage pipeline (unchanged control).
// ---------------------------------------------------------------------------
#define A_SK   0
#define A_SQ   4096
#define A_ID   4608
#define A_ST   5120
#define A_PH   0
#define A_PL   10240
#define A_KH   20480
#define A_KL   29184
#define A_STB  37888
#define ATTN_SMEM (A_ST + 2*A_STB)

__global__ __launch_bounds__(256) void attn_mma(
    const __nv_bfloat16* __restrict__ kxh, const __nv_bfloat16* __restrict__ kxl,
    float* __restrict__ score,
    __nv_bfloat16* __restrict__ aout_h, __nv_bfloat16* __restrict__ aout_l)
{
    extern __shared__ char smem[];
    const uint32_t sb = smem_u32(smem);
    float* sksA = (float*)smem;
    float* sqsA = (float*)(smem + A_SQ);
    float* idsA = (float*)(smem + A_ID);

    const int tid = threadIdx.x;
    const int wid = tid >> 5, lane = tid & 31;
    const int g = lane >> 2, tig = lane & 3;
    const int hb = blockIdx.y;
    const int h = hb >> 4, b = hb & 15;
    const int i0 = blockIdx.x << 7;
    const int wm = (wid & 1) << 6;
    const int wn = (wid >> 1) << 5;
    const uint32_t lrow = lane & 15, lhalf = (lane >> 4) * 16;

    for (int t = tid; t < LEN; t += 256) sksA[t] = g_sk[hb * LEN + t];
    if (tid < 128) {
        sqsA[tid] = g_sq[hb * LEN + i0 + tid];
        idsA[tid] = g_invd[hb * LEN + i0 + tid];
    }
    __syncthreads();

    const int prow = tid >> 1;
    const int pj0 = (tid & 1) * 16;
    const float sqi = sqsA[prow];
    const float idi = idsA[prow];
    float* srow = score + ((size_t)hb * LEN + i0 + prow) * LEN + pj0;
    const uint32_t p_off = prow * 80 + pj0 * 2;

    const int krow = tid >> 3;
    const int kseg = tid & 7;
    const __nv_bfloat16* gKh = kxh + (size_t)(b * 1024 + krow) * 1024 + h * 128 + kseg * 8;
    const __nv_bfloat16* gKl = kxl + (size_t)(b * 1024 + krow) * 1024 + h * 128 + kseg * 8;
    const uint32_t k_off = krow * 272 + kseg * 16;

    float acc[4][4][4];
    #pragma unroll
    for (int i = 0; i < 4; i++)
        #pragma unroll
        for (int j = 0; j < 4; j++)
            #pragma unroll
            for (int r = 0; r < 4; r++) acc[i][j][r] = 0.0f;

    #define GEN_CHUNK(ch, stbase) do {                                          \
        const int jb = (ch) * 32;                                               \
        float pf[16]; uint32_t hp[8], lp[8];                                    \
        _Pragma("unroll")                                                       \
        for (int u = 0; u < 16; u++)                                            \
            pf[u] = exp_tanh(sqi + sksA[jb + pj0 + u]) * idi;                   \
        _Pragma("unroll")                                                       \
        for (int u = 0; u < 8; u++) {                                           \
            float p0 = pf[2*u], p1 = pf[2*u+1];                                 \
            hp[u] = pack_bf16(p0, p1);                                          \
            float r0 = p0 - __bfloat162float(__float2bfloat16(p0));             \
            float r1 = p1 - __bfloat162float(__float2bfloat16(p1));             \
            lp[u] = pack_bf16(r0, r1);                                          \
        }                                                                       \
        *(float4*)(srow + jb)      = {pf[0], pf[1], pf[2], pf[3]};              \
        *(float4*)(srow + jb + 4)  = {pf[4], pf[5], pf[6], pf[7]};              \
        *(float4*)(srow + jb + 8)  = {pf[8], pf[9], pf[10], pf[11]};            \
        *(float4*)(srow + jb + 12) = {pf[12], pf[13], pf[14], pf[15]};          \
        asm volatile("st.shared.v4.b32 [%0], {%1,%2,%3,%4};" ::                 \
            "r"((stbase) + A_PH + p_off), "r"(hp[0]), "r"(hp[1]), "r"(hp[2]), "r"(hp[3]) : "memory"); \
        asm volatile("st.shared.v4.b32 [%0], {%1,%2,%3,%4};" ::                 \
            "r"((stbase) + A_PH + p_off + 16), "r"(hp[4]), "r"(hp[5]), "r"(hp[6]), "r"(hp[7]) : "memory"); \
        asm volatile("st.shared.v4.b32 [%0], {%1,%2,%3,%4};" ::                 \
            "r"((stbase) + A_PL + p_off), "r"(lp[0]), "r"(lp[1]), "r"(lp[2]), "r"(lp[3]) : "memory"); \
        asm volatile("st.shared.v4.b32 [%0], {%1,%2,%3,%4};" ::                 \
            "r"((stbase) + A_PL + p_off + 16), "r"(lp[4]), "r"(lp[5]), "r"(lp[6]), "r"(lp[7]) : "memory"); \
        const size_t gkoff = (size_t)jb * 1024;                                 \
        cpa16((stbase) + A_KH + k_off,       gKh + gkoff);                      \
        cpa16((stbase) + A_KH + k_off + 128, gKh + gkoff + 64);                 \
        cpa16((stbase) + A_KL + k_off,       gKl + gkoff);                      \
        cpa16((stbase) + A_KL + k_off + 128, gKl + gkoff + 64);                 \
    } while (0)

    GEN_CHUNK(0, sb + A_ST);
    CPA_COMMIT();
    GEN_CHUNK(1, sb + A_ST + A_STB);
    CPA_COMMIT();
    CPA_WAIT1();
    __syncthreads();

    for (int c = 0; c < 32; c++) {
        const uint32_t stb = sb + A_ST + (c & 1) * A_STB;
        #pragma unroll
        for (int ks = 0; ks < 2; ks++) {
            const uint32_t kb = ks * 32;
            uint32_t ph[4][4], pl[4][4], bh[4][2], bl[4][2];
            #pragma unroll
            for (int mf = 0; mf < 4; mf++) {
                uint32_t ra = stb + (wm + mf*16 + lrow) * 80 + kb + lhalf;
                ldsm4(ph[mf], ra + A_PH);
                ldsm4(pl[mf], ra + A_PL);
            }
            #pragma unroll
            for (int nh = 0; nh < 2; nh++) {
                uint32_t rb = stb + (ks*16 + lrow) * 272 + (wn + nh*16) * 2 + lhalf;
                uint32_t t[4];
                ldsm4t(t, rb + A_KH);
                bh[nh*2][0] = t[0]; bh[nh*2][1] = t[1];
                bh[nh*2+1][0] = t[2]; bh[nh*2+1][1] = t[3];
                ldsm4t(t, rb + A_KL);
                bl[nh*2][0] = t[0]; bl[nh*2][1] = t[1];
                bl[nh*2+1][0] = t[2]; bl[nh*2+1][1] = t[3];
            }
            #pragma unroll
            for (int mf = 0; mf < 4; mf++)
                #pragma unroll
                for (int nf = 0; nf < 4; nf++) {
                    mma_bf16(acc[mf][nf], ph[mf], bh[nf]);
                    mma_bf16(acc[mf][nf], ph[mf], bl[nf]);
                    mma_bf16(acc[mf][nf], pl[mf], bh[nf]);
                }
        }
        __syncthreads();
        if (c + 2 < 32) GEN_CHUNK(c + 2, stb);
        CPA_COMMIT();
        CPA_WAIT1();
        __syncthreads();
    }

    #pragma unroll
    for (int mf = 0; mf < 4; mf++) {
        #pragma unroll
        for (int nf = 0; nf < 4; nf++) {
            const int r0 = wm + mf * 16 + g;
            const int col = wn + nf * 8 + 2 * tig;
            float v00 = acc[mf][nf][0], v01 = acc[mf][nf][1];
            float v10 = acc[mf][nf][2], v11 = acc[mf][nf][3];
            size_t o0 = (size_t)(b * 1024 + i0 + r0) * 1024 + h * 128 + col;
            size_t o1 = (size_t)(b * 1024 + i0 + r0 + 8) * 1024 + h * 128 + col;
            *(uint32_t*)(aout_h + o0) = pack_bf16(v00, v01);
            *(uint32_t*)(aout_h + o1) = pack_bf16(v10, v11);
            float r00 = v00 - __bfloat162float(__float2bfloat16(v00));
            float r01 = v01 - __bfloat162float(__float2bfloat16(v01));
            float r10 = v10 - __bfloat162float(__float2bfloat16(v10));
            float r11 = v11 - __bfloat162float(__float2bfloat16(v11));
            *(uint32_t*)(aout_l + o0) = pack_bf16(r00, r01);
            *(uint32_t*)(aout_l + o1) = pack_bf16(r10, r11);
        }
    }
}

// ---------------------------------------------------------------------------
extern "C" void kernel_launch(void* const* d_in, const int* in_sizes, int n_in,
                              void* d_out, int out_size)
{
    const float* k  = (const float*)d_in[0];
    const float* q  = (const float*)d_in[1];
    const float* Wk = (const float*)d_in[2];
    const float* bk = (const float*)d_in[3];
    const float* Wq = (const float*)d_in[4];
    const float* bq = (const float*)d_in[5];
    const float* w  = (const float*)d_in[6];
    const float* Wp = (const float*)d_in[7];
    const float* bp = (const float*)d_in[8];
    float* out   = (float*)d_out;
    float* score = out + (size_t)MROWS * EMB;

    __nv_bfloat16 *kh,*kl,*kxh,*kxl,*ah,*al,*wkh,*wkl,*wph,*wpl;
    cudaGetSymbolAddress((void**)&kh,  g_kh);   cudaGetSymbolAddress((void**)&kl,  g_kl);
    cudaGetSymbolAddress((void**)&kxh, g_kxh);  cudaGetSymbolAddress((void**)&kxl, g_kxl);
    cudaGetSymbolAddress((void**)&ah,  g_ah);   cudaGetSymbolAddress((void**)&al,  g_al);
    cudaGetSymbolAddress((void**)&wkh, g_Wkh);  cudaGetSymbolAddress((void**)&wkl, g_Wkl);
    cudaGetSymbolAddress((void**)&wph, g_Wph);  cudaGetSymbolAddress((void**)&wpl, g_Wpl);

    cudaFuncSetAttribute(gemm_mma, cudaFuncAttributeMaxDynamicSharedMemorySize, GEMM_SMEM);
    cudaFuncSetAttribute(attn_mma, cudaFuncAttributeMaxDynamicSharedMemorySize, ATTN_SMEM);

    const int nBig = MROWS * EMB;
    const int nW   = EMB * EMB;
    dim3 gg(EMB / 128, MROWS / 128);

    // Launch order chosen so the 6th launch (ncu -s 5 -c 1) is gemm_mma.
    split_kernel<<<nBig/16/256, 256>>>(k, kh, kl, nBig);      // 1
    split_kernel<<<nW/16/256, 256>>>(Wk, wkh, wkl, nW);       // 2
    vkq_kernel<<<dim3(NHEAD, 16), 256>>>(Wk, bk, Wq, bq, w);  // 3
    sksq_kernel<<<MROWS/8, 256>>>(k, q);                      // 4
    denom_kernel<<<NHB * 8, 128>>>();                         // 5
    gemm_mma<<<gg, 256, GEMM_SMEM>>>(kh, kl, wkh, wkl, bk, nullptr, kxh, kxl); // 6 <- profiled
    split_kernel<<<nW/16/256, 256>>>(Wp, wph, wpl, nW);       // 7
    attn_mma<<<dim3(8, NHB), 256, ATTN_SMEM>>>(kxh, kxl, score, ah, al);       // 8
    gemm_mma<<<gg, 256, GEMM_SMEM>>>(ah, al, wph, wpl, bp, out, nullptr, nullptr); // 9
}